// round 2
// baseline (speedup 1.0000x reference)
#include <cuda_runtime.h>
#include <math.h>

#define D_MODEL 768
#define D_HID   3072
#define NUM_EXPERTS 8
#define TOPK    2
#define NTOK    2048
#define NSLOT   (NTOK * TOPK)

// ---------------- device scratch (no runtime allocation allowed) ----------------
__device__ float g_hidden[NSLOT * D_HID];   // gelu(x@W1) per routed slot
__device__ float g_y[NSLOT * D_MODEL];      // per-slot FFN output
__device__ int   g_cnt[NUM_EXPERTS];        // tokens routed to each expert
__device__ int   g_rows[NUM_EXPERTS * NTOK];// slot ids per expert
__device__ float g_wt[NSLOT];               // normalized top-k weight per slot

// ---------------- reset (device globals persist across graph replays) ----------
__global__ void reset_kernel() {
    if (threadIdx.x < NUM_EXPERTS) g_cnt[threadIdx.x] = 0;
}

// ---------------- router: logits -> top2 -> normalized weights -----------------
__global__ void router_kernel(const float* __restrict__ x,
                              const float* __restrict__ gw) {
    __shared__ float xs[D_MODEL];
    __shared__ float logits[NUM_EXPERTS];
    const int n = blockIdx.x;
    const float* xr = x + (size_t)n * D_MODEL;
    for (int i = threadIdx.x; i < D_MODEL; i += blockDim.x) xs[i] = xr[i];
    __syncthreads();

    const int w = threadIdx.x >> 5, lane = threadIdx.x & 31;
    if (w < NUM_EXPERTS) {
        float s = 0.f;
        for (int d = lane; d < D_MODEL; d += 32)
            s += xs[d] * gw[d * NUM_EXPERTS + w];
        #pragma unroll
        for (int o = 16; o; o >>= 1) s += __shfl_xor_sync(0xffffffffu, s, o);
        if (lane == 0) logits[w] = s;
    }
    __syncthreads();

    if (threadIdx.x == 0) {
        // top-1 (first occurrence on ties, like lax.top_k)
        int i0 = 0; float l0 = logits[0];
        #pragma unroll
        for (int e = 1; e < NUM_EXPERTS; e++)
            if (logits[e] > l0) { l0 = logits[e]; i0 = e; }
        int i1 = -1; float l1 = -INFINITY;
        #pragma unroll
        for (int e = 0; e < NUM_EXPERTS; e++)
            if (e != i0 && logits[e] > l1) { l1 = logits[e]; i1 = e; }
        // renormalized top-2 softmax weights: exp(l)/sum_top2 exp(l)
        float e1 = expf(l1 - l0);
        float inv = 1.f / (1.f + e1);
        float w0 = inv, w1 = e1 * inv;

        int p0 = atomicAdd(&g_cnt[i0], 1);
        g_rows[i0 * NTOK + p0] = n * 2 + 0;
        g_wt[n * 2 + 0] = w0;
        int p1 = atomicAdd(&g_cnt[i1], 1);
        g_rows[i1 * NTOK + p1] = n * 2 + 1;
        g_wt[n * 2 + 1] = w1;
    }
}

// ---------------- grouped GEMM body: 128x128x8 SIMT fp32 -----------------------
// C[r, n] = act( sum_k A[src(r), k] * B_e[k, n] + bias_e[n] ), rows gathered per expert.
template<bool GELU, bool HALVE_ROW>
__device__ __forceinline__ void gemm_body(
    const float* __restrict__ A, int lda,
    const float* __restrict__ B, int ldb, int Kdim,
    const float* __restrict__ bias,
    float* __restrict__ C, int ldc)
{
    const int e = blockIdx.z;
    const int cnt = g_cnt[e];
    const int m0 = blockIdx.y * 128;
    if (m0 >= cnt) return;
    const int n0 = blockIdx.x * 128;
    const int* rows = g_rows + e * NTOK;
    const float* Be = B + (size_t)e * Kdim * ldb;

    __shared__ float As[8][128];
    __shared__ float Bs[8][128];

    const int tid = threadIdx.x;
    // A tile load: 128 rows x 8 cols, one float4 per thread
    const int arow = tid >> 1;
    const int ac   = (tid & 1) * 4;
    const int gr   = m0 + arow;
    const bool avalid = gr < cnt;
    const float* aptr = nullptr;
    if (avalid) {
        int slot = rows[gr];
        int src  = HALVE_ROW ? (slot >> 1) : slot;
        aptr = A + (size_t)src * lda;
    }
    // B tile load: 8 rows x 128 cols, one float4 per thread
    const int brow = tid >> 5;
    const int bc   = (tid & 31) * 4;

    const int tm = (tid >> 4) * 8;
    const int tn = (tid & 15) * 8;

    float acc[8][8];
    #pragma unroll
    for (int i = 0; i < 8; i++)
        #pragma unroll
        for (int j = 0; j < 8; j++) acc[i][j] = 0.f;

    for (int k0 = 0; k0 < Kdim; k0 += 8) {
        float4 av = avalid ? *(const float4*)(aptr + k0 + ac)
                           : make_float4(0.f, 0.f, 0.f, 0.f);
        float4 bv = *(const float4*)(Be + (size_t)(k0 + brow) * ldb + n0 + bc);
        __syncthreads();
        As[ac + 0][arow] = av.x;
        As[ac + 1][arow] = av.y;
        As[ac + 2][arow] = av.z;
        As[ac + 3][arow] = av.w;
        *(float4*)&Bs[brow][bc] = bv;
        __syncthreads();
        #pragma unroll
        for (int kk = 0; kk < 8; kk++) {
            float a[8], b[8];
            *(float4*)(a + 0) = *(const float4*)&As[kk][tm];
            *(float4*)(a + 4) = *(const float4*)&As[kk][tm + 4];
            *(float4*)(b + 0) = *(const float4*)&Bs[kk][tn];
            *(float4*)(b + 4) = *(const float4*)&Bs[kk][tn + 4];
            #pragma unroll
            for (int i = 0; i < 8; i++)
                #pragma unroll
                for (int j = 0; j < 8; j++)
                    acc[i][j] += a[i] * b[j];
        }
    }

    // epilogue
    float bvs[8];
    const float* bp = bias + (size_t)e * (GELU ? D_HID : D_MODEL) + n0 + tn;
    #pragma unroll
    for (int j = 0; j < 8; j++) bvs[j] = bp[j];

    #pragma unroll
    for (int i = 0; i < 8; i++) {
        int r = m0 + tm + i;
        if (r < cnt) {
            int slot = rows[r];
            float* crow = C + (size_t)slot * ldc + n0 + tn;
            float o[8];
            #pragma unroll
            for (int j = 0; j < 8; j++) {
                float v = acc[i][j] + bvs[j];
                if (GELU) v = 0.5f * v * (1.f + erff(v * 0.70710678118654752f));
                o[j] = v;
            }
            *(float4*)(crow + 0) = *(float4*)(o + 0);
            *(float4*)(crow + 4) = *(float4*)(o + 4);
        }
    }
}

__global__ void __launch_bounds__(256)
gemm1_kernel(const float* __restrict__ x, const float* __restrict__ w1,
             const float* __restrict__ b1) {
    gemm_body<true, true>(x, D_MODEL, w1, D_HID, D_MODEL, b1, g_hidden, D_HID);
}

__global__ void __launch_bounds__(256)
gemm2_kernel(const float* __restrict__ w2, const float* __restrict__ b2) {
    gemm_body<false, false>(g_hidden, D_HID, w2, D_MODEL, D_HID, b2, g_y, D_MODEL);
}

// ---------------- weighted combine across the 2 slots per token ----------------
__global__ void combine_kernel(float* __restrict__ out) {
    int idx = blockIdx.x * blockDim.x + threadIdx.x;      // over NTOK * D_MODEL/4
    int n  = idx / (D_MODEL / 4);
    int d4 = (idx % (D_MODEL / 4)) * 4;
    float w0 = g_wt[2 * n], w1 = g_wt[2 * n + 1];
    float4 y0 = *(const float4*)&g_y[(size_t)(2 * n + 0) * D_MODEL + d4];
    float4 y1 = *(const float4*)&g_y[(size_t)(2 * n + 1) * D_MODEL + d4];
    float4 o;
    o.x = w0 * y0.x + w1 * y1.x;
    o.y = w0 * y0.y + w1 * y1.y;
    o.z = w0 * y0.z + w1 * y1.z;
    o.w = w0 * y0.w + w1 * y1.w;
    *(float4*)&out[(size_t)n * D_MODEL + d4] = o;
}

// ---------------- launcher ------------------------------------------------------
extern "C" void kernel_launch(void* const* d_in, const int* in_sizes, int n_in,
                              void* d_out, int out_size) {
    const float* x      = (const float*)d_in[0];
    const float* gate_w = (const float*)d_in[1];
    const float* w1     = (const float*)d_in[2];
    const float* b1     = (const float*)d_in[3];
    const float* w2     = (const float*)d_in[4];
    const float* b2     = (const float*)d_in[5];
    float* out = (float*)d_out;

    reset_kernel<<<1, 32>>>();
    router_kernel<<<NTOK, 256>>>(x, gate_w);
    gemm1_kernel<<<dim3(D_HID / 128, NTOK / 128, NUM_EXPERTS), 256>>>(x, w1, b1);
    gemm2_kernel<<<dim3(D_MODEL / 128, NTOK / 128, NUM_EXPERTS), 256>>>(w2, b2);
    combine_kernel<<<(NTOK * (D_MODEL / 4)) / 256, 256>>>(out);
}

// round 5
// speedup vs baseline: 2.0780x; 2.0780x over previous
#include <cuda_runtime.h>
#include <math.h>

#define D_MODEL 768
#define D_HID   3072
#define NUM_EXPERTS 8
#define TOPK    2
#define NTOK    2048
#define NSLOT   (NTOK * TOPK)

// ---------------- device scratch (no runtime allocation allowed) ----------------
__device__ float g_hidden[NSLOT * D_HID];   // gelu(x@W1) per routed slot
__device__ float g_y[NSLOT * D_MODEL];      // per-slot FFN output
__device__ int   g_cnt[NUM_EXPERTS];        // tokens routed to each expert
__device__ int   g_rows[NUM_EXPERTS * NTOK];// slot ids per expert
__device__ float g_wt[NSLOT];               // normalized top-k weight per slot

// ---------------- reset (device globals persist across graph replays) ----------
__global__ void reset_kernel() {
    if (threadIdx.x < NUM_EXPERTS) g_cnt[threadIdx.x] = 0;
}

// ---------------- router: logits -> top2 -> normalized weights -----------------
// fp32 exact, code identical to R2 (expert assignment must match reference).
__global__ void router_kernel(const float* __restrict__ x,
                              const float* __restrict__ gw) {
    __shared__ float xs[D_MODEL];
    __shared__ float logits[NUM_EXPERTS];
    const int n = blockIdx.x;
    const float* xr = x + (size_t)n * D_MODEL;
    for (int i = threadIdx.x; i < D_MODEL; i += blockDim.x) xs[i] = xr[i];
    __syncthreads();

    const int w = threadIdx.x >> 5, lane = threadIdx.x & 31;
    if (w < NUM_EXPERTS) {
        float s = 0.f;
        for (int d = lane; d < D_MODEL; d += 32)
            s += xs[d] * gw[d * NUM_EXPERTS + w];
        #pragma unroll
        for (int o = 16; o; o >>= 1) s += __shfl_xor_sync(0xffffffffu, s, o);
        if (lane == 0) logits[w] = s;
    }
    __syncthreads();

    if (threadIdx.x == 0) {
        int i0 = 0; float l0 = logits[0];
        #pragma unroll
        for (int e = 1; e < NUM_EXPERTS; e++)
            if (logits[e] > l0) { l0 = logits[e]; i0 = e; }
        int i1 = -1; float l1 = -INFINITY;
        #pragma unroll
        for (int e = 0; e < NUM_EXPERTS; e++)
            if (e != i0 && logits[e] > l1) { l1 = logits[e]; i1 = e; }
        float e1 = expf(l1 - l0);
        float inv = 1.f / (1.f + e1);
        float w0 = inv, w1 = e1 * inv;

        int p0 = atomicAdd(&g_cnt[i0], 1);
        g_rows[i0 * NTOK + p0] = n * 2 + 0;
        g_wt[n * 2 + 0] = w0;
        int p1 = atomicAdd(&g_cnt[i1], 1);
        g_rows[i1 * NTOK + p1] = n * 2 + 1;
        g_wt[n * 2 + 1] = w1;
    }
}

// ---------------- tf32 helpers --------------------------------------------------
__device__ __forceinline__ unsigned f2tf32(float f) {
    unsigned u;
    asm("cvt.rna.tf32.f32 %0, %1;" : "=r"(u) : "f"(f));
    return u;
}

__device__ __forceinline__ void mma_tf32(float* c,
                                         unsigned a0, unsigned a1, unsigned a2, unsigned a3,
                                         unsigned b0, unsigned b1) {
    asm volatile(
        "mma.sync.aligned.m16n8k8.row.col.f32.tf32.tf32.f32 "
        "{%0,%1,%2,%3}, {%4,%5,%6,%7}, {%8,%9}, {%0,%1,%2,%3};"
        : "+f"(c[0]), "+f"(c[1]), "+f"(c[2]), "+f"(c[3])
        : "r"(a0), "r"(a1), "r"(a2), "r"(a3), "r"(b0), "r"(b1));
}

// ---------------- grouped tensor-core GEMM: BM=64, BN=128, BK=16 ----------------
// C[r, n] = act( sum_k A[src(r), k] * B_e[k, n] + bias_e[n] ), rows gathered per expert.
// 8 warps, warp tile 32x32 (2 m-frags x 4 n-frags of m16n8k8).
template<bool GELU, bool HALVE_ROW>
__device__ __forceinline__ void gemm_tc(
    const float* __restrict__ A, int lda,
    const float* __restrict__ B, int ldb, int Kdim,
    const float* __restrict__ bias,
    float* __restrict__ C, int ldc)
{
    constexpr int BM = 64, BN = 128, BK = 16;
    constexpr int ASTR = BK + 4;    // 20: banks (20m+k)%32 bijective over a warp
    constexpr int BSTR = BN + 8;    // 136: banks (8k+n)%32 bijective over a warp

    const int e = blockIdx.z;
    const int cnt = g_cnt[e];
    const int m0 = blockIdx.y * BM;
    if (m0 >= cnt) return;
    const int n0 = blockIdx.x * BN;
    const int* rows = g_rows + e * NTOK;
    const float* Be = B + (size_t)e * Kdim * ldb;

    __shared__ unsigned As[BM * ASTR];
    __shared__ unsigned Bs[BK * BSTR];

    const int tid  = threadIdx.x;
    const int warp = tid >> 5;
    const int lane = tid & 31;
    const int grp  = lane >> 2;     // 0..7
    const int qid  = lane & 3;      // 0..3

    const int warp_m = warp & 1;    // 0..1  (m span 32)
    const int warp_n = warp >> 1;   // 0..3  (n span 32)
    const int cbase  = warp_n * 32;

    // A staging: 64x16 floats = 256 float4; thread -> (m = tid>>2, kq = (tid&3)*4)
    const int am = tid >> 2;
    const int akq = (tid & 3) * 4;
    const int gr = m0 + am;
    const bool avalid = gr < cnt;
    const float* aptr = A;  // dummy
    if (avalid) {
        int slot = rows[gr];
        int src = HALVE_ROW ? (slot >> 1) : slot;
        aptr = A + (size_t)src * lda + akq;
    }
    // B staging: 16x128 floats = 512 float4; 2 per thread
    const int bk0 = tid >> 5;            // 0..7   (it=0)
    const int bn4 = (lane) * 4;          // 0..124
    const float* bptr0 = Be + (size_t)bk0 * ldb + n0 + bn4;
    const float* bptr1 = bptr0 + (size_t)8 * ldb;   // k rows 8..15

    float acc[2][4][4];
    #pragma unroll
    for (int i = 0; i < 2; i++)
        #pragma unroll
        for (int j = 0; j < 4; j++)
            #pragma unroll
            for (int q = 0; q < 4; q++) acc[i][j][q] = 0.f;

    const int ktiles = Kdim / BK;

    // prologue: stage tile 0
    float4 a_st = avalid ? *(const float4*)(aptr)
                         : make_float4(0.f, 0.f, 0.f, 0.f);
    float4 b_st0 = *(const float4*)(bptr0);
    float4 b_st1 = *(const float4*)(bptr1);

    for (int t = 0; t < ktiles; t++) {
        __syncthreads();
        // commit staged tile to smem (rounded to tf32)
        {
            uint4 av = make_uint4(f2tf32(a_st.x), f2tf32(a_st.y),
                                  f2tf32(a_st.z), f2tf32(a_st.w));
            *(uint4*)&As[am * ASTR + akq] = av;
            uint4 bv0 = make_uint4(f2tf32(b_st0.x), f2tf32(b_st0.y),
                                   f2tf32(b_st0.z), f2tf32(b_st0.w));
            *(uint4*)&Bs[bk0 * BSTR + bn4] = bv0;
            uint4 bv1 = make_uint4(f2tf32(b_st1.x), f2tf32(b_st1.y),
                                   f2tf32(b_st1.z), f2tf32(b_st1.w));
            *(uint4*)&Bs[(bk0 + 8) * BSTR + bn4] = bv1;
        }
        __syncthreads();
        // prefetch next tile (latency overlapped by MMA below)
        if (t + 1 < ktiles) {
            int k0 = (t + 1) * BK;
            a_st = avalid ? *(const float4*)(aptr + k0)
                          : make_float4(0.f, 0.f, 0.f, 0.f);
            b_st0 = *(const float4*)(bptr0 + (size_t)k0 * ldb);
            b_st1 = *(const float4*)(bptr1 + (size_t)k0 * ldb);
        }
        // compute: 2 k-steps of 8
        #pragma unroll
        for (int s = 0; s < 2; s++) {
            const int ks = s * 8;
            unsigned a[2][4];
            #pragma unroll
            for (int i = 0; i < 2; i++) {
                int mr = warp_m * 32 + i * 16 + grp;
                a[i][0] = As[mr * ASTR + ks + qid];
                a[i][1] = As[(mr + 8) * ASTR + ks + qid];
                a[i][2] = As[mr * ASTR + ks + qid + 4];
                a[i][3] = As[(mr + 8) * ASTR + ks + qid + 4];
            }
            unsigned b[4][2];
            #pragma unroll
            for (int j = 0; j < 4; j++) {
                int nc = cbase + j * 8 + grp;
                b[j][0] = Bs[(ks + qid) * BSTR + nc];
                b[j][1] = Bs[(ks + qid + 4) * BSTR + nc];
            }
            #pragma unroll
            for (int j = 0; j < 4; j++)
                #pragma unroll
                for (int i = 0; i < 2; i++)
                    mma_tf32(acc[i][j], a[i][0], a[i][1], a[i][2], a[i][3],
                             b[j][0], b[j][1]);
        }
    }

    // epilogue: bias (+ GELU), scatter rows via slot ids
    const float* bp = bias + (size_t)e * ldc;
    float2 bv[4];
    #pragma unroll
    for (int j = 0; j < 4; j++) {
        int c = n0 + cbase + j * 8 + 2 * qid;
        bv[j] = *(const float2*)(bp + c);
    }
    #pragma unroll
    for (int i = 0; i < 2; i++) {
        int rbase = m0 + warp_m * 32 + i * 16 + grp;
        #pragma unroll
        for (int h = 0; h < 2; h++) {       // c0/c1 (row) vs c2/c3 (row+8)
            int r = rbase + h * 8;
            if (r < cnt) {
                int slot = rows[r];
                float* crow = C + (size_t)slot * ldc;
                #pragma unroll
                for (int j = 0; j < 4; j++) {
                    int c = n0 + cbase + j * 8 + 2 * qid;
                    float v0 = acc[i][j][2 * h + 0] + bv[j].x;
                    float v1 = acc[i][j][2 * h + 1] + bv[j].y;
                    if (GELU) {
                        v0 = 0.5f * v0 * (1.f + erff(v0 * 0.70710678118654752f));
                        v1 = 0.5f * v1 * (1.f + erff(v1 * 0.70710678118654752f));
                    }
                    *(float2*)(crow + c) = make_float2(v0, v1);
                }
            }
        }
    }
}

__global__ void __launch_bounds__(256, 2)
gemm1_kernel(const float* __restrict__ x, const float* __restrict__ w1,
             const float* __restrict__ b1) {
    gemm_tc<true, true>(x, D_MODEL, w1, D_HID, D_MODEL, b1, g_hidden, D_HID);
}

__global__ void __launch_bounds__(256, 2)
gemm2_kernel(const float* __restrict__ w2, const float* __restrict__ b2) {
    gemm_tc<false, false>(g_hidden, D_HID, w2, D_MODEL, D_HID, b2, g_y, D_MODEL);
}

// ---------------- weighted combine across the 2 slots per token ----------------
__global__ void combine_kernel(float* __restrict__ out) {
    int idx = blockIdx.x * blockDim.x + threadIdx.x;      // over NTOK * D_MODEL/4
    int n  = idx / (D_MODEL / 4);
    int d4 = (idx % (D_MODEL / 4)) * 4;
    float w0 = g_wt[2 * n], w1 = g_wt[2 * n + 1];
    float4 y0 = *(const float4*)&g_y[(size_t)(2 * n + 0) * D_MODEL + d4];
    float4 y1 = *(const float4*)&g_y[(size_t)(2 * n + 1) * D_MODEL + d4];
    float4 o;
    o.x = w0 * y0.x + w1 * y1.x;
    o.y = w0 * y0.y + w1 * y1.y;
    o.z = w0 * y0.z + w1 * y1.z;
    o.w = w0 * y0.w + w1 * y1.w;
    *(float4*)&out[(size_t)n * D_MODEL + d4] = o;
}

// ---------------- launcher ------------------------------------------------------
extern "C" void kernel_launch(void* const* d_in, const int* in_sizes, int n_in,
                              void* d_out, int out_size) {
    const float* x      = (const float*)d_in[0];
    const float* gate_w = (const float*)d_in[1];
    const float* w1     = (const float*)d_in[2];
    const float* b1     = (const float*)d_in[3];
    const float* w2     = (const float*)d_in[4];
    const float* b2     = (const float*)d_in[5];
    float* out = (float*)d_out;

    reset_kernel<<<1, 32>>>();
    router_kernel<<<NTOK, 256>>>(x, gate_w);
    gemm1_kernel<<<dim3(D_HID / 128, NTOK / 64, NUM_EXPERTS), 256>>>(x, w1, b1);
    gemm2_kernel<<<dim3(D_MODEL / 128, NTOK / 64, NUM_EXPERTS), 256>>>(w2, b2);
    combine_kernel<<<(NTOK * (D_MODEL / 4)) / 256, 256>>>(out);
}

// round 6
// speedup vs baseline: 2.0786x; 1.0003x over previous
#include <cuda_runtime.h>
#include <math.h>

#define D_MODEL 768
#define D_HID   3072
#define NUM_EXPERTS 8
#define TOPK    2
#define NTOK    2048
#define NSLOT   (NTOK * TOPK)

// ---------------- device scratch (no runtime allocation allowed) ----------------
__device__ float g_hidden[NSLOT * D_HID];   // gelu(x@W1) per routed slot
__device__ float g_y[NSLOT * D_MODEL];      // per-slot FFN output
__device__ int   g_cnt[NUM_EXPERTS];        // tokens routed to each expert
__device__ int   g_rows[NUM_EXPERTS * NTOK];// slot ids per expert
__device__ float g_wt[NSLOT];               // normalized top-k weight per slot

// ---------------- reset (device globals persist across graph replays) ----------
__global__ void reset_kernel() {
    if (threadIdx.x < NUM_EXPERTS) g_cnt[threadIdx.x] = 0;
}

// ---------------- router: logits -> top2 -> normalized weights -----------------
// fp32 exact, code identical to R2 (expert assignment must match reference).
__global__ void router_kernel(const float* __restrict__ x,
                              const float* __restrict__ gw) {
    __shared__ float xs[D_MODEL];
    __shared__ float logits[NUM_EXPERTS];
    const int n = blockIdx.x;
    const float* xr = x + (size_t)n * D_MODEL;
    for (int i = threadIdx.x; i < D_MODEL; i += blockDim.x) xs[i] = xr[i];
    __syncthreads();

    const int w = threadIdx.x >> 5, lane = threadIdx.x & 31;
    if (w < NUM_EXPERTS) {
        float s = 0.f;
        for (int d = lane; d < D_MODEL; d += 32)
            s += xs[d] * gw[d * NUM_EXPERTS + w];
        #pragma unroll
        for (int o = 16; o; o >>= 1) s += __shfl_xor_sync(0xffffffffu, s, o);
        if (lane == 0) logits[w] = s;
    }
    __syncthreads();

    if (threadIdx.x == 0) {
        int i0 = 0; float l0 = logits[0];
        #pragma unroll
        for (int e = 1; e < NUM_EXPERTS; e++)
            if (logits[e] > l0) { l0 = logits[e]; i0 = e; }
        int i1 = -1; float l1 = -INFINITY;
        #pragma unroll
        for (int e = 0; e < NUM_EXPERTS; e++)
            if (e != i0 && logits[e] > l1) { l1 = logits[e]; i1 = e; }
        float e1 = expf(l1 - l0);
        float inv = 1.f / (1.f + e1);
        float w0 = inv, w1 = e1 * inv;

        int p0 = atomicAdd(&g_cnt[i0], 1);
        g_rows[i0 * NTOK + p0] = n * 2 + 0;
        g_wt[n * 2 + 0] = w0;
        int p1 = atomicAdd(&g_cnt[i1], 1);
        g_rows[i1 * NTOK + p1] = n * 2 + 1;
        g_wt[n * 2 + 1] = w1;
    }
}

// ---------------- tf32 helpers --------------------------------------------------
__device__ __forceinline__ unsigned f2tf32(float f) {
    unsigned u;
    asm("cvt.rna.tf32.f32 %0, %1;" : "=r"(u) : "f"(f));
    return u;
}

__device__ __forceinline__ void mma_tf32(float* c,
                                         unsigned a0, unsigned a1, unsigned a2, unsigned a3,
                                         unsigned b0, unsigned b1) {
    asm volatile(
        "mma.sync.aligned.m16n8k8.row.col.f32.tf32.tf32.f32 "
        "{%0,%1,%2,%3}, {%4,%5,%6,%7}, {%8,%9}, {%0,%1,%2,%3};"
        : "+f"(c[0]), "+f"(c[1]), "+f"(c[2]), "+f"(c[3])
        : "r"(a0), "r"(a1), "r"(a2), "r"(a3), "r"(b0), "r"(b1));
}

// ---------------- grouped tensor-core GEMM: BM=64, BN=128, BK=16 ----------------
// C[r, n] = act( sum_k A[src(r), k] * B_e[k, n] + bias_e[n] ), rows gathered per expert.
// 8 warps, warp tile 32x32 (2 m-frags x 4 n-frags of m16n8k8).
template<bool GELU, bool HALVE_ROW>
__device__ __forceinline__ void gemm_tc(
    const float* __restrict__ A, int lda,
    const float* __restrict__ B, int ldb, int Kdim,
    const float* __restrict__ bias,
    float* __restrict__ C, int ldc)
{
    constexpr int BM = 64, BN = 128, BK = 16;
    constexpr int ASTR = BK + 4;    // 20: banks (20m+k)%32 bijective over a warp
    constexpr int BSTR = BN + 8;    // 136: banks (8k+n)%32 bijective over a warp

    const int e = blockIdx.z;
    const int cnt = g_cnt[e];
    const int m0 = blockIdx.y * BM;
    if (m0 >= cnt) return;
    const int n0 = blockIdx.x * BN;
    const int* rows = g_rows + e * NTOK;
    const float* Be = B + (size_t)e * Kdim * ldb;

    __shared__ unsigned As[BM * ASTR];
    __shared__ unsigned Bs[BK * BSTR];

    const int tid  = threadIdx.x;
    const int warp = tid >> 5;
    const int lane = tid & 31;
    const int grp  = lane >> 2;     // 0..7
    const int qid  = lane & 3;      // 0..3

    const int warp_m = warp & 1;    // 0..1  (m span 32)
    const int warp_n = warp >> 1;   // 0..3  (n span 32)
    const int cbase  = warp_n * 32;

    // A staging: 64x16 floats = 256 float4; thread -> (m = tid>>2, kq = (tid&3)*4)
    const int am = tid >> 2;
    const int akq = (tid & 3) * 4;
    const int gr = m0 + am;
    const bool avalid = gr < cnt;
    const float* aptr = A;  // dummy
    if (avalid) {
        int slot = rows[gr];
        int src = HALVE_ROW ? (slot >> 1) : slot;
        aptr = A + (size_t)src * lda + akq;
    }
    // B staging: 16x128 floats = 512 float4; 2 per thread
    const int bk0 = tid >> 5;            // 0..7   (it=0)
    const int bn4 = (lane) * 4;          // 0..124
    const float* bptr0 = Be + (size_t)bk0 * ldb + n0 + bn4;
    const float* bptr1 = bptr0 + (size_t)8 * ldb;   // k rows 8..15

    float acc[2][4][4];
    #pragma unroll
    for (int i = 0; i < 2; i++)
        #pragma unroll
        for (int j = 0; j < 4; j++)
            #pragma unroll
            for (int q = 0; q < 4; q++) acc[i][j][q] = 0.f;

    const int ktiles = Kdim / BK;

    // prologue: stage tile 0
    float4 a_st = avalid ? *(const float4*)(aptr)
                         : make_float4(0.f, 0.f, 0.f, 0.f);
    float4 b_st0 = *(const float4*)(bptr0);
    float4 b_st1 = *(const float4*)(bptr1);

    for (int t = 0; t < ktiles; t++) {
        __syncthreads();
        // commit staged tile to smem (rounded to tf32)
        {
            uint4 av = make_uint4(f2tf32(a_st.x), f2tf32(a_st.y),
                                  f2tf32(a_st.z), f2tf32(a_st.w));
            *(uint4*)&As[am * ASTR + akq] = av;
            uint4 bv0 = make_uint4(f2tf32(b_st0.x), f2tf32(b_st0.y),
                                   f2tf32(b_st0.z), f2tf32(b_st0.w));
            *(uint4*)&Bs[bk0 * BSTR + bn4] = bv0;
            uint4 bv1 = make_uint4(f2tf32(b_st1.x), f2tf32(b_st1.y),
                                   f2tf32(b_st1.z), f2tf32(b_st1.w));
            *(uint4*)&Bs[(bk0 + 8) * BSTR + bn4] = bv1;
        }
        __syncthreads();
        // prefetch next tile (latency overlapped by MMA below)
        if (t + 1 < ktiles) {
            int k0 = (t + 1) * BK;
            a_st = avalid ? *(const float4*)(aptr + k0)
                          : make_float4(0.f, 0.f, 0.f, 0.f);
            b_st0 = *(const float4*)(bptr0 + (size_t)k0 * ldb);
            b_st1 = *(const float4*)(bptr1 + (size_t)k0 * ldb);
        }
        // compute: 2 k-steps of 8
        #pragma unroll
        for (int s = 0; s < 2; s++) {
            const int ks = s * 8;
            unsigned a[2][4];
            #pragma unroll
            for (int i = 0; i < 2; i++) {
                int mr = warp_m * 32 + i * 16 + grp;
                a[i][0] = As[mr * ASTR + ks + qid];
                a[i][1] = As[(mr + 8) * ASTR + ks + qid];
                a[i][2] = As[mr * ASTR + ks + qid + 4];
                a[i][3] = As[(mr + 8) * ASTR + ks + qid + 4];
            }
            unsigned b[4][2];
            #pragma unroll
            for (int j = 0; j < 4; j++) {
                int nc = cbase + j * 8 + grp;
                b[j][0] = Bs[(ks + qid) * BSTR + nc];
                b[j][1] = Bs[(ks + qid + 4) * BSTR + nc];
            }
            #pragma unroll
            for (int j = 0; j < 4; j++)
                #pragma unroll
                for (int i = 0; i < 2; i++)
                    mma_tf32(acc[i][j], a[i][0], a[i][1], a[i][2], a[i][3],
                             b[j][0], b[j][1]);
        }
    }

    // epilogue: bias (+ GELU), scatter rows via slot ids
    const float* bp = bias + (size_t)e * ldc;
    float2 bv[4];
    #pragma unroll
    for (int j = 0; j < 4; j++) {
        int c = n0 + cbase + j * 8 + 2 * qid;
        bv[j] = *(const float2*)(bp + c);
    }
    #pragma unroll
    for (int i = 0; i < 2; i++) {
        int rbase = m0 + warp_m * 32 + i * 16 + grp;
        #pragma unroll
        for (int h = 0; h < 2; h++) {       // c0/c1 (row) vs c2/c3 (row+8)
            int r = rbase + h * 8;
            if (r < cnt) {
                int slot = rows[r];
                float* crow = C + (size_t)slot * ldc;
                #pragma unroll
                for (int j = 0; j < 4; j++) {
                    int c = n0 + cbase + j * 8 + 2 * qid;
                    float v0 = acc[i][j][2 * h + 0] + bv[j].x;
                    float v1 = acc[i][j][2 * h + 1] + bv[j].y;
                    if (GELU) {
                        v0 = 0.5f * v0 * (1.f + erff(v0 * 0.70710678118654752f));
                        v1 = 0.5f * v1 * (1.f + erff(v1 * 0.70710678118654752f));
                    }
                    *(float2*)(crow + c) = make_float2(v0, v1);
                }
            }
        }
    }
}

__global__ void __launch_bounds__(256, 2)
gemm1_kernel(const float* __restrict__ x, const float* __restrict__ w1,
             const float* __restrict__ b1) {
    gemm_tc<true, true>(x, D_MODEL, w1, D_HID, D_MODEL, b1, g_hidden, D_HID);
}

__global__ void __launch_bounds__(256, 2)
gemm2_kernel(const float* __restrict__ w2, const float* __restrict__ b2) {
    gemm_tc<false, false>(g_hidden, D_HID, w2, D_MODEL, D_HID, b2, g_y, D_MODEL);
}

// ---------------- weighted combine across the 2 slots per token ----------------
__global__ void combine_kernel(float* __restrict__ out) {
    int idx = blockIdx.x * blockDim.x + threadIdx.x;      // over NTOK * D_MODEL/4
    int n  = idx / (D_MODEL / 4);
    int d4 = (idx % (D_MODEL / 4)) * 4;
    float w0 = g_wt[2 * n], w1 = g_wt[2 * n + 1];
    float4 y0 = *(const float4*)&g_y[(size_t)(2 * n + 0) * D_MODEL + d4];
    float4 y1 = *(const float4*)&g_y[(size_t)(2 * n + 1) * D_MODEL + d4];
    float4 o;
    o.x = w0 * y0.x + w1 * y1.x;
    o.y = w0 * y0.y + w1 * y1.y;
    o.z = w0 * y0.z + w1 * y1.z;
    o.w = w0 * y0.w + w1 * y1.w;
    *(float4*)&out[(size_t)n * D_MODEL + d4] = o;
}

// ---------------- launcher ------------------------------------------------------
extern "C" void kernel_launch(void* const* d_in, const int* in_sizes, int n_in,
                              void* d_out, int out_size) {
    const float* x      = (const float*)d_in[0];
    const float* gate_w = (const float*)d_in[1];
    const float* w1     = (const float*)d_in[2];
    const float* b1     = (const float*)d_in[3];
    const float* w2     = (const float*)d_in[4];
    const float* b2     = (const float*)d_in[5];
    float* out = (float*)d_out;

    reset_kernel<<<1, 32>>>();
    router_kernel<<<NTOK, 256>>>(x, gate_w);
    gemm1_kernel<<<dim3(D_HID / 128, NTOK / 64, NUM_EXPERTS), 256>>>(x, w1, b1);
    gemm2_kernel<<<dim3(D_MODEL / 128, NTOK / 64, NUM_EXPERTS), 256>>>(w2, b2);
    combine_kernel<<<(NTOK * (D_MODEL / 4)) / 256, 256>>>(out);
}